// round 3
// baseline (speedup 1.0000x reference)
#include <cuda_runtime.h>
#include <math.h>

#define D 128
#define NGRAPH 128
#define MAXN 100000

// Scratch (static __device__ arrays per allocation rules)
__device__ float g_t0[(size_t)MAXN * D];
__device__ float g_t1[(size_t)MAXN * D];
__device__ float g_gate[MAXN];

// ---------------------------------------------------------------------------
// GEMM: out[M,128] = f_in(A) @ W, with optional fused epilogues.
//   in_mode : 0 = A as-is; 1 = relu(A + ib); 2 = A + ib (NO relu)
//   out_mode: 0 = store acc; 2 = gate: g[r] = sum_j relu(acc_j+ob_j)*gw2_j + gb2
// W (64KB) in dynamic smem. Block = 256 thr (8 warps). Each warp computes
// 8 rows; each lane owns 4 cols -> 32 accumulators. 64 rows per block-iter.
// ---------------------------------------------------------------------------
#define ROWS_PER_WARP 8
#define GEMM_WARPS 8
#define ROWS_PER_BLK (ROWS_PER_WARP * GEMM_WARPS)   // 64

__global__ __launch_bounds__(256) void gemm128_kernel(
    const float* __restrict__ A, const float* __restrict__ W,
    const float* __restrict__ ib, const float* __restrict__ ob,
    const float* __restrict__ gw2, const float* __restrict__ gb2,
    float* __restrict__ out, float* __restrict__ gate,
    int M, int in_mode, int out_mode)
{
    extern __shared__ float sh[];
    float* Wsh  = sh;                  // D*D floats (64KB)
    float* rows = sh + D * D;          // ROWS_PER_BLK * D floats (32KB)

    for (int i = threadIdx.x; i < D * D; i += blockDim.x) Wsh[i] = W[i];

    const int warp = threadIdx.x >> 5;
    const int lane = threadIdx.x & 31;
    const int col  = lane << 2;

    float ob0 = 0.f, ob1 = 0.f, ob2v = 0.f, ob3 = 0.f;
    float w20 = 0.f, w21 = 0.f, w22 = 0.f, w23 = 0.f, gb2v = 0.f;
    if (out_mode == 2) {
        ob0 = ob[col]; ob1 = ob[col + 1]; ob2v = ob[col + 2]; ob3 = ob[col + 3];
        w20 = gw2[col]; w21 = gw2[col + 1]; w22 = gw2[col + 2]; w23 = gw2[col + 3];
        gb2v = gb2[0];
    }
    __syncthreads();

    const int ngroups = (M + ROWS_PER_BLK - 1) / ROWS_PER_BLK;
    for (int grp = blockIdx.x; grp < ngroups; grp += gridDim.x) {
        const int r0 = grp * ROWS_PER_BLK;

        // Cooperative load of 64 rows into smem (fused input bias / bias+relu).
        {
            const int nf4 = ROWS_PER_BLK * (D / 4);
            for (int i = threadIdx.x; i < nf4; i += blockDim.x) {
                const int rr = i >> 5;           // row within group
                const int cc = (i & 31) << 2;    // col
                const int r  = r0 + rr;
                float4 v = make_float4(0.f, 0.f, 0.f, 0.f);
                if (r < M) v = *(const float4*)&A[(size_t)r * D + cc];
                if (in_mode) {
                    v.x += ib[cc];     v.y += ib[cc + 1];
                    v.z += ib[cc + 2]; v.w += ib[cc + 3];
                    if (in_mode == 1) {   // relu only for mode 1
                        v.x = fmaxf(v.x, 0.f); v.y = fmaxf(v.y, 0.f);
                        v.z = fmaxf(v.z, 0.f); v.w = fmaxf(v.w, 0.f);
                    }
                }
                *(float4*)&rows[rr * D + cc] = v;
            }
        }
        __syncthreads();

        float acc[ROWS_PER_WARP][4];
        #pragma unroll
        for (int r = 0; r < ROWS_PER_WARP; r++)
            acc[r][0] = acc[r][1] = acc[r][2] = acc[r][3] = 0.f;

        const float* rb = &rows[warp * ROWS_PER_WARP * D];
        #pragma unroll 4
        for (int k = 0; k < D; k++) {
            const float4 w = *(const float4*)&Wsh[k * D + col];
            #pragma unroll
            for (int r = 0; r < ROWS_PER_WARP; r++) {
                const float a = rb[r * D + k];
                acc[r][0] = fmaf(a, w.x, acc[r][0]);
                acc[r][1] = fmaf(a, w.y, acc[r][1]);
                acc[r][2] = fmaf(a, w.z, acc[r][2]);
                acc[r][3] = fmaf(a, w.w, acc[r][3]);
            }
        }

        if (out_mode == 0) {
            #pragma unroll
            for (int r = 0; r < ROWS_PER_WARP; r++) {
                const int row = r0 + warp * ROWS_PER_WARP + r;
                if (row < M)
                    *(float4*)&out[(size_t)row * D + col] =
                        make_float4(acc[r][0], acc[r][1], acc[r][2], acc[r][3]);
            }
        } else {
            #pragma unroll
            for (int r = 0; r < ROWS_PER_WARP; r++) {
                const int row = r0 + warp * ROWS_PER_WARP + r;
                float v = fmaxf(acc[r][0] + ob0, 0.f) * w20
                        + fmaxf(acc[r][1] + ob1, 0.f) * w21
                        + fmaxf(acc[r][2] + ob2v, 0.f) * w22
                        + fmaxf(acc[r][3] + ob3, 0.f) * w23;
                #pragma unroll
                for (int o = 16; o; o >>= 1) v += __shfl_xor_sync(0xffffffffu, v, o);
                if (lane == 0 && row < M) gate[row] = v + gb2v;
            }
        }
        __syncthreads();
    }
}

// ---------------------------------------------------------------------------
// Edge scatter: out[dst[e], :] += ew[e] * A[src[e], :]
// One warp per edge; each lane handles one float4 via red.global.add.v4.f32
// ---------------------------------------------------------------------------
__global__ __launch_bounds__(256) void scatter_kernel(
    const float* __restrict__ A, const int* __restrict__ src,
    const int* __restrict__ dst, const float* __restrict__ ew,
    float* __restrict__ out, int NE)
{
    const int gw   = (blockIdx.x * blockDim.x + threadIdx.x) >> 5;
    const int lane = threadIdx.x & 31;
    const int nw   = (gridDim.x * blockDim.x) >> 5;
    for (int e = gw; e < NE; e += nw) {
        const int s   = src[e];
        const int d   = dst[e];
        const float w = ew[e];
        float4 v = *(const float4*)&A[(size_t)s * D + (lane << 2)];
        v.x *= w; v.y *= w; v.z *= w; v.w *= w;
        float* p = &out[(size_t)d * D + (lane << 2)];
        asm volatile("red.global.add.v4.f32 [%0], {%1,%2,%3,%4};"
                     :: "l"(p), "f"(v.x), "f"(v.y), "f"(v.z), "f"(v.w)
                     : "memory");
    }
}

// ---------------------------------------------------------------------------
// Per-graph softmax attention pool + final MLP, one block per graph.
// batch is sorted -> segment bounds via binary search (no atomics).
// h[node] = T1[node] + b2 (conv2 bias fused here).
// ---------------------------------------------------------------------------
#define EBUF_CAP 4096
__global__ __launch_bounds__(128) void attn_kernel(
    const float* __restrict__ T1, const float* __restrict__ b2,
    const float* __restrict__ gate, const int* __restrict__ batch,
    const float* __restrict__ l1W, const float* __restrict__ l1b,
    const float* __restrict__ l2W, const float* __restrict__ l2b,
    float* __restrict__ out, int M)
{
    __shared__ float ebuf[EBUF_CAP];
    __shared__ float sacc[D];
    __shared__ float red[4];
    __shared__ int bounds[2];

    const int b    = blockIdx.x;
    const int tid  = threadIdx.x;
    const int lane = tid & 31;
    const int warp = tid >> 5;

    if (tid < 2) {
        const int target = b + tid;
        int lo = 0, hi = M;
        while (lo < hi) {
            const int mid = (lo + hi) >> 1;
            if (batch[mid] < target) lo = mid + 1; else hi = mid;
        }
        bounds[tid] = lo;
    }
    __syncthreads();
    const int lo  = bounds[0];
    const int hi  = bounds[1];
    const int len = hi - lo;

    // pass 1: segment max of gate
    float m = -INFINITY;
    for (int i = tid; i < len; i += D) m = fmaxf(m, gate[lo + i]);
    #pragma unroll
    for (int o = 16; o; o >>= 1) m = fmaxf(m, __shfl_xor_sync(0xffffffffu, m, o));
    if (lane == 0) red[warp] = m;
    __syncthreads();
    m = fmaxf(fmaxf(red[0], red[1]), fmaxf(red[2], red[3]));
    __syncthreads();

    // pass 2: exp + denom
    float s = 0.f;
    for (int i = tid; i < len; i += D) {
        const float e = expf(gate[lo + i] - m);
        if (i < EBUF_CAP) ebuf[i] = e;
        s += e;
    }
    #pragma unroll
    for (int o = 16; o; o >>= 1) s += __shfl_xor_sync(0xffffffffu, s, o);
    if (lane == 0) red[warp] = s;
    __syncthreads();
    const float denom = red[0] + red[1] + red[2] + red[3];
    const float inv = 1.f / (denom + 1e-16f);

    // pass 3: p[c] = inv * sum_i e_i * (T1[i][c] + b2[c]); thread = column c
    float acc = 0.f;
    const float b2c = b2[tid];
    for (int i = 0; i < len; i++) {
        const float w = (i < EBUF_CAP) ? ebuf[i] : expf(gate[lo + i] - m);
        acc = fmaf(w, T1[(size_t)(lo + i) * D + tid] + b2c, acc);
    }
    acc *= inv;
    __syncthreads();
    sacc[tid] = acc;
    __syncthreads();

    // final MLP: out[b] = relu(p @ l1W + l1b) . l2W + l2b
    float u = l1b[tid];
    #pragma unroll 8
    for (int k = 0; k < D; k++) u = fmaf(sacc[k], l1W[k * D + tid], u);
    u = fmaxf(u, 0.f) * l2W[tid];
    #pragma unroll
    for (int o = 16; o; o >>= 1) u += __shfl_xor_sync(0xffffffffu, u, o);
    if (lane == 0) red[warp] = u;
    __syncthreads();
    if (tid == 0) out[b] = red[0] + red[1] + red[2] + red[3] + l2b[0];
}

// ---------------------------------------------------------------------------
extern "C" void kernel_launch(void* const* d_in, const int* in_sizes, int n_in,
                              void* d_out, int out_size)
{
    const float* x     = (const float*)d_in[0];
    const int*   ei    = (const int*)  d_in[1];
    const float* ea    = (const float*)d_in[2];
    const int*   batch = (const int*)  d_in[3];
    const float* W1    = (const float*)d_in[4];
    const float* b1    = (const float*)d_in[5];
    const float* W2    = (const float*)d_in[6];
    const float* b2    = (const float*)d_in[7];
    const float* gW1   = (const float*)d_in[8];
    const float* gb1   = (const float*)d_in[9];
    const float* gW2   = (const float*)d_in[10];
    const float* gb2   = (const float*)d_in[11];
    const float* l1W   = (const float*)d_in[12];
    const float* l1b   = (const float*)d_in[13];
    const float* l2W   = (const float*)d_in[14];
    const float* l2b   = (const float*)d_in[15];
    float* out = (float*)d_out;

    const int M  = in_sizes[0] / D;
    const int NE = in_sizes[1] / 2;
    const int* src = ei;
    const int* dst = ei + NE;

    float *t0, *t1, *gate;
    cudaGetSymbolAddress((void**)&t0,   g_t0);
    cudaGetSymbolAddress((void**)&t1,   g_t1);
    cudaGetSymbolAddress((void**)&gate, g_gate);

    const size_t SMEM = (size_t)(D * D + ROWS_PER_BLK * D) * sizeof(float); // 96KB
    cudaFuncSetAttribute(gemm128_kernel, cudaFuncAttributeMaxDynamicSharedMemorySize, (int)SMEM);

    const int GB = 296;  // 2 blocks/SM (96KB smem each)

    // conv1: t0 = x @ W1 ; t1 = scatter(t0) ; (relu(+b1) fused into next gemm)
    gemm128_kernel<<<GB, 256, SMEM>>>(x, W1, nullptr, nullptr, nullptr, nullptr,
                                      t0, nullptr, M, 0, 0);
    cudaMemsetAsync(t1, 0, (size_t)M * D * sizeof(float), 0);
    scatter_kernel<<<2048, 256>>>(t0, src, dst, ea, t1, NE);

    // conv2: t0 = relu(t1 + b1) @ W2 ; t1 = scatter(t0)  (b2 fused downstream)
    gemm128_kernel<<<GB, 256, SMEM>>>(t1, W2, b1, nullptr, nullptr, nullptr,
                                      t0, nullptr, M, 1, 0);
    cudaMemsetAsync(t1, 0, (size_t)M * D * sizeof(float), 0);
    scatter_kernel<<<2048, 256>>>(t0, src, dst, ea, t1, NE);

    // gate[r] = relu((t1[r]+b2) @ gW1 + gb1) . gW2 + gb2  (bias-only input, mode 2)
    gemm128_kernel<<<GB, 256, SMEM>>>(t1, gW1, b2, gb1, gW2, gb2,
                                      nullptr, gate, M, 2, 2);

    // per-graph softmax pool + final MLP
    attn_kernel<<<NGRAPH, 128>>>(t1, b2, gate, batch, l1W, l1b, l2W, l2b, out, M);
}

// round 6
// speedup vs baseline: 1.2580x; 1.2580x over previous
#include <cuda_runtime.h>
#include <math.h>

#define D 128
#define NGRAPH 128
#define MAXN 100000
#define MAXE 1600000
#define SCAN_BLK 512

// Scratch (static __device__ arrays per allocation rules)
__device__ float g_t0[(size_t)MAXN * D];
__device__ float g_t1[(size_t)MAXN * D];
__device__ float g_gate[MAXN];
__device__ int   g_rowptr[MAXN];
__device__ int   g_cursor[MAXN];     // deg during count; row-end after fill
__device__ int   g_bsums[SCAN_BLK];
__device__ int2  g_edges[MAXE];      // (src, __float_as_int(ew)) CSR by dst

// ---------------------------------------------------------------------------
// GEMM: out[M,128] = f_in(A) @ W, with optional fused epilogues.
//   in_mode : 0 = A as-is; 1 = relu(A + ib); 2 = A + ib (NO relu)
//   out_mode: 0 = store acc; 2 = gate: g[r] = sum_j relu(acc_j+ob_j)*gw2_j + gb2
// ---------------------------------------------------------------------------
#define ROWS_PER_WARP 8
#define GEMM_WARPS 8
#define ROWS_PER_BLK (ROWS_PER_WARP * GEMM_WARPS)   // 64

__global__ __launch_bounds__(256) void gemm128_kernel(
    const float* __restrict__ A, const float* __restrict__ W,
    const float* __restrict__ ib, const float* __restrict__ ob,
    const float* __restrict__ gw2, const float* __restrict__ gb2,
    float* __restrict__ out, float* __restrict__ gate,
    int M, int in_mode, int out_mode)
{
    extern __shared__ float sh[];
    float* Wsh  = sh;                  // D*D floats (64KB)
    float* rows = sh + D * D;          // ROWS_PER_BLK * D floats (32KB)

    for (int i = threadIdx.x; i < D * D; i += blockDim.x) Wsh[i] = W[i];

    const int warp = threadIdx.x >> 5;
    const int lane = threadIdx.x & 31;
    const int col  = lane << 2;

    float ob0 = 0.f, ob1 = 0.f, ob2v = 0.f, ob3 = 0.f;
    float w20 = 0.f, w21 = 0.f, w22 = 0.f, w23 = 0.f, gb2v = 0.f;
    if (out_mode == 2) {
        ob0 = ob[col]; ob1 = ob[col + 1]; ob2v = ob[col + 2]; ob3 = ob[col + 3];
        w20 = gw2[col]; w21 = gw2[col + 1]; w22 = gw2[col + 2]; w23 = gw2[col + 3];
        gb2v = gb2[0];
    }
    __syncthreads();

    const int ngroups = (M + ROWS_PER_BLK - 1) / ROWS_PER_BLK;
    for (int grp = blockIdx.x; grp < ngroups; grp += gridDim.x) {
        const int r0 = grp * ROWS_PER_BLK;

        {
            const int nf4 = ROWS_PER_BLK * (D / 4);
            for (int i = threadIdx.x; i < nf4; i += blockDim.x) {
                const int rr = i >> 5;
                const int cc = (i & 31) << 2;
                const int r  = r0 + rr;
                float4 v = make_float4(0.f, 0.f, 0.f, 0.f);
                if (r < M) v = *(const float4*)&A[(size_t)r * D + cc];
                if (in_mode) {
                    v.x += ib[cc];     v.y += ib[cc + 1];
                    v.z += ib[cc + 2]; v.w += ib[cc + 3];
                    if (in_mode == 1) {
                        v.x = fmaxf(v.x, 0.f); v.y = fmaxf(v.y, 0.f);
                        v.z = fmaxf(v.z, 0.f); v.w = fmaxf(v.w, 0.f);
                    }
                }
                *(float4*)&rows[rr * D + cc] = v;
            }
        }
        __syncthreads();

        float acc[ROWS_PER_WARP][4];
        #pragma unroll
        for (int r = 0; r < ROWS_PER_WARP; r++)
            acc[r][0] = acc[r][1] = acc[r][2] = acc[r][3] = 0.f;

        const float* rb = &rows[warp * ROWS_PER_WARP * D];
        #pragma unroll 4
        for (int k = 0; k < D; k++) {
            const float4 w = *(const float4*)&Wsh[k * D + col];
            #pragma unroll
            for (int r = 0; r < ROWS_PER_WARP; r++) {
                const float a = rb[r * D + k];
                acc[r][0] = fmaf(a, w.x, acc[r][0]);
                acc[r][1] = fmaf(a, w.y, acc[r][1]);
                acc[r][2] = fmaf(a, w.z, acc[r][2]);
                acc[r][3] = fmaf(a, w.w, acc[r][3]);
            }
        }

        if (out_mode == 0) {
            #pragma unroll
            for (int r = 0; r < ROWS_PER_WARP; r++) {
                const int row = r0 + warp * ROWS_PER_WARP + r;
                if (row < M)
                    *(float4*)&out[(size_t)row * D + col] =
                        make_float4(acc[r][0], acc[r][1], acc[r][2], acc[r][3]);
            }
        } else {
            #pragma unroll
            for (int r = 0; r < ROWS_PER_WARP; r++) {
                const int row = r0 + warp * ROWS_PER_WARP + r;
                float v = fmaxf(acc[r][0] + ob0, 0.f) * w20
                        + fmaxf(acc[r][1] + ob1, 0.f) * w21
                        + fmaxf(acc[r][2] + ob2v, 0.f) * w22
                        + fmaxf(acc[r][3] + ob3, 0.f) * w23;
                #pragma unroll
                for (int o = 16; o; o >>= 1) v += __shfl_xor_sync(0xffffffffu, v, o);
                if (lane == 0 && row < M) gate[row] = v + gb2v;
            }
        }
        __syncthreads();
    }
}

// ---------------------------------------------------------------------------
// CSR build: degree count -> exclusive scan -> bucket fill
// ---------------------------------------------------------------------------
__global__ __launch_bounds__(256) void deg_kernel(
    const int* __restrict__ dst, int* __restrict__ deg, int NE)
{
    for (int e = blockIdx.x * 256 + threadIdx.x; e < NE; e += gridDim.x * 256)
        atomicAdd(&deg[dst[e]], 1);
}

// Exclusive scan stage A: per-block scan of SCAN_BLK entries + block sums
__global__ __launch_bounds__(SCAN_BLK) void scanA_kernel(
    const int* __restrict__ deg, int* __restrict__ rowptr,
    int* __restrict__ bsums, int n)
{
    __shared__ int s[SCAN_BLK];
    const int t = threadIdx.x;
    const int i = blockIdx.x * SCAN_BLK + t;
    const int v = (i < n) ? deg[i] : 0;
    s[t] = v;
    __syncthreads();
    #pragma unroll
    for (int o = 1; o < SCAN_BLK; o <<= 1) {
        const int add = (t >= o) ? s[t - o] : 0;
        __syncthreads();
        s[t] += add;
        __syncthreads();
    }
    if (i < n) rowptr[i] = s[t] - v;          // exclusive
    if (t == SCAN_BLK - 1) bsums[blockIdx.x] = s[t];
}

// Stage B: scan of block sums (single block, nblk <= SCAN_BLK)
__global__ __launch_bounds__(SCAN_BLK) void scanB_kernel(int* __restrict__ bsums, int nblk)
{
    __shared__ int s[SCAN_BLK];
    const int t = threadIdx.x;
    const int v = (t < nblk) ? bsums[t] : 0;
    s[t] = v;
    __syncthreads();
    #pragma unroll
    for (int o = 1; o < SCAN_BLK; o <<= 1) {
        const int add = (t >= o) ? s[t - o] : 0;
        __syncthreads();
        s[t] += add;
        __syncthreads();
    }
    if (t < nblk) bsums[t] = s[t] - v;        // exclusive
}

// Stage C: add block offsets; init cursor = rowptr
__global__ __launch_bounds__(SCAN_BLK) void scanC_kernel(
    int* __restrict__ rowptr, int* __restrict__ cursor,
    const int* __restrict__ bsums, int n)
{
    const int i = blockIdx.x * SCAN_BLK + threadIdx.x;
    if (i < n) {
        const int r = rowptr[i] + bsums[blockIdx.x];
        rowptr[i] = r;
        cursor[i] = r;
    }
}

__global__ __launch_bounds__(256) void fill_kernel(
    const int* __restrict__ src, const int* __restrict__ dst,
    const float* __restrict__ ew, int* __restrict__ cursor,
    int2* __restrict__ edges, int NE)
{
    for (int e = blockIdx.x * 256 + threadIdx.x; e < NE; e += gridDim.x * 256) {
        const int p = atomicAdd(&cursor[dst[e]], 1);
        edges[p] = make_int2(src[e], __float_as_int(ew[e]));
    }
}

// ---------------------------------------------------------------------------
// CSR gather-aggregate: out[n,:] = sum_{e in csr[n]} ew_e * A[src_e, :]
// One warp per node; lane owns one float4 column slice. No atomics, no memset.
// ---------------------------------------------------------------------------
__global__ __launch_bounds__(256) void gather_kernel(
    const float* __restrict__ A, const int* __restrict__ rowptr,
    const int* __restrict__ rowend, const int2* __restrict__ edges,
    float* __restrict__ out, int M)
{
    const int node = ((blockIdx.x * 256 + threadIdx.x) >> 5);
    if (node >= M) return;
    const int lane = threadIdx.x & 31;
    const int col  = lane << 2;

    const int start = rowptr[node];
    const int end   = rowend[node];

    float4 acc = make_float4(0.f, 0.f, 0.f, 0.f);
    int2 e_next = (start < end) ? edges[start] : make_int2(0, 0);
    for (int j = start; j < end; j++) {
        const int2 e = e_next;
        if (j + 1 < end) e_next = edges[j + 1];        // prefetch next edge
        const float w = __int_as_float(e.y);
        const float4 v = *(const float4*)&A[(size_t)e.x * D + col];
        acc.x = fmaf(w, v.x, acc.x);
        acc.y = fmaf(w, v.y, acc.y);
        acc.z = fmaf(w, v.z, acc.z);
        acc.w = fmaf(w, v.w, acc.w);
    }
    *(float4*)&out[(size_t)node * D + col] = acc;
}

// ---------------------------------------------------------------------------
// Per-graph softmax attention pool + final MLP, one block per graph.
// ---------------------------------------------------------------------------
#define EBUF_CAP 4096
__global__ __launch_bounds__(128) void attn_kernel(
    const float* __restrict__ T1, const float* __restrict__ b2,
    const float* __restrict__ gate, const int* __restrict__ batch,
    const float* __restrict__ l1W, const float* __restrict__ l1b,
    const float* __restrict__ l2W, const float* __restrict__ l2b,
    float* __restrict__ out, int M)
{
    __shared__ float ebuf[EBUF_CAP];
    __shared__ float sacc[D];
    __shared__ float red[4];
    __shared__ int bounds[2];

    const int b    = blockIdx.x;
    const int tid  = threadIdx.x;
    const int lane = tid & 31;
    const int warp = tid >> 5;

    if (tid < 2) {
        const int target = b + tid;
        int lo = 0, hi = M;
        while (lo < hi) {
            const int mid = (lo + hi) >> 1;
            if (batch[mid] < target) lo = mid + 1; else hi = mid;
        }
        bounds[tid] = lo;
    }
    __syncthreads();
    const int lo  = bounds[0];
    const int hi  = bounds[1];
    const int len = hi - lo;

    float m = -INFINITY;
    for (int i = tid; i < len; i += D) m = fmaxf(m, gate[lo + i]);
    #pragma unroll
    for (int o = 16; o; o >>= 1) m = fmaxf(m, __shfl_xor_sync(0xffffffffu, m, o));
    if (lane == 0) red[warp] = m;
    __syncthreads();
    m = fmaxf(fmaxf(red[0], red[1]), fmaxf(red[2], red[3]));
    __syncthreads();

    float s = 0.f;
    for (int i = tid; i < len; i += D) {
        const float e = expf(gate[lo + i] - m);
        if (i < EBUF_CAP) ebuf[i] = e;
        s += e;
    }
    #pragma unroll
    for (int o = 16; o; o >>= 1) s += __shfl_xor_sync(0xffffffffu, s, o);
    if (lane == 0) red[warp] = s;
    __syncthreads();
    const float denom = red[0] + red[1] + red[2] + red[3];
    const float inv = 1.f / (denom + 1e-16f);

    float acc = 0.f;
    const float b2c = b2[tid];
    for (int i = 0; i < len; i++) {
        const float w = (i < EBUF_CAP) ? ebuf[i] : expf(gate[lo + i] - m);
        acc = fmaf(w, T1[(size_t)(lo + i) * D + tid] + b2c, acc);
    }
    acc *= inv;
    __syncthreads();
    sacc[tid] = acc;
    __syncthreads();

    float u = l1b[tid];
    #pragma unroll 8
    for (int k = 0; k < D; k++) u = fmaf(sacc[k], l1W[k * D + tid], u);
    u = fmaxf(u, 0.f) * l2W[tid];
    #pragma unroll
    for (int o = 16; o; o >>= 1) u += __shfl_xor_sync(0xffffffffu, u, o);
    if (lane == 0) red[warp] = u;
    __syncthreads();
    if (tid == 0) out[b] = red[0] + red[1] + red[2] + red[3] + l2b[0];
}

// ---------------------------------------------------------------------------
extern "C" void kernel_launch(void* const* d_in, const int* in_sizes, int n_in,
                              void* d_out, int out_size)
{
    const float* x     = (const float*)d_in[0];
    const int*   ei    = (const int*)  d_in[1];
    const float* ea    = (const float*)d_in[2];
    const int*   batch = (const int*)  d_in[3];
    const float* W1    = (const float*)d_in[4];
    const float* b1    = (const float*)d_in[5];
    const float* W2    = (const float*)d_in[6];
    const float* b2    = (const float*)d_in[7];
    const float* gW1   = (const float*)d_in[8];
    const float* gb1   = (const float*)d_in[9];
    const float* gW2   = (const float*)d_in[10];
    const float* gb2   = (const float*)d_in[11];
    const float* l1W   = (const float*)d_in[12];
    const float* l1b   = (const float*)d_in[13];
    const float* l2W   = (const float*)d_in[14];
    const float* l2b   = (const float*)d_in[15];
    float* out = (float*)d_out;

    const int M  = in_sizes[0] / D;
    const int NE = in_sizes[1] / 2;
    const int* src = ei;
    const int* dst = ei + NE;

    float *t0, *t1, *gate;
    int *rowptr, *cursor, *bsums;
    int2 *edges;
    cudaGetSymbolAddress((void**)&t0,     g_t0);
    cudaGetSymbolAddress((void**)&t1,     g_t1);
    cudaGetSymbolAddress((void**)&gate,   g_gate);
    cudaGetSymbolAddress((void**)&rowptr, g_rowptr);
    cudaGetSymbolAddress((void**)&cursor, g_cursor);
    cudaGetSymbolAddress((void**)&bsums,  g_bsums);
    cudaGetSymbolAddress((void**)&edges,  g_edges);

    const size_t SMEM = (size_t)(D * D + ROWS_PER_BLK * D) * sizeof(float); // 96KB
    cudaFuncSetAttribute(gemm128_kernel, cudaFuncAttributeMaxDynamicSharedMemorySize, (int)SMEM);

    const int GB     = 296;                       // 2 blocks/SM for GEMM
    const int EBLK   = 2048;                      // edge-parallel kernels (grid-stride)
    const int NBLK   = (M + SCAN_BLK - 1) / SCAN_BLK;   // scan blocks (<= SCAN_BLK)
    const int GATB   = (M * 32 + 255) / 256;      // warp-per-node gather

    // ---- CSR build (once; reused by both convs) ----
    cudaMemsetAsync(cursor, 0, (size_t)M * sizeof(int), 0);
    deg_kernel <<<EBLK, 256>>>(dst, cursor, NE);
    scanA_kernel<<<NBLK, SCAN_BLK>>>(cursor, rowptr, bsums, M);
    scanB_kernel<<<1, SCAN_BLK>>>(bsums, NBLK);
    scanC_kernel<<<NBLK, SCAN_BLK>>>(rowptr, cursor, bsums, M);
    fill_kernel<<<EBLK, 256>>>(src, dst, ea, cursor, edges, NE);
    // after fill: cursor[n] = row end

    // conv1: t0 = x @ W1 ; t1 = csr_gather(t0)
    gemm128_kernel<<<GB, 256, SMEM>>>(x, W1, nullptr, nullptr, nullptr, nullptr,
                                      t0, nullptr, M, 0, 0);
    gather_kernel<<<GATB, 256>>>(t0, rowptr, cursor, edges, t1, M);

    // conv2: t0 = relu(t1 + b1) @ W2 ; t1 = csr_gather(t0)
    gemm128_kernel<<<GB, 256, SMEM>>>(t1, W2, b1, nullptr, nullptr, nullptr,
                                      t0, nullptr, M, 1, 0);
    gather_kernel<<<GATB, 256>>>(t0, rowptr, cursor, edges, t1, M);

    // gate[r] = relu((t1[r]+b2) @ gW1 + gb1) . gW2 + gb2
    gemm128_kernel<<<GB, 256, SMEM>>>(t1, gW1, b2, gb1, gW2, gb2,
                                      nullptr, gate, M, 2, 2);

    // per-graph softmax pool + final MLP
    attn_kernel<<<NGRAPH, 128>>>(t1, b2, gate, batch, l1W, l1b, l2W, l2b, out, M);
}

// round 8
// speedup vs baseline: 1.2787x; 1.0164x over previous
#include <cuda_runtime.h>
#include <math.h>

#define D 128
#define NGRAPH 128
#define MAXN 100000
#define MAXE 1600000
#define SCAN_BLK 512

// Scratch (static __device__ arrays per allocation rules)
__device__ float g_t0[(size_t)MAXN * D];
__device__ float g_t1[(size_t)MAXN * D];
__device__ float g_gate[MAXN];
__device__ int   g_rowptr[MAXN];
__device__ int   g_cursor[MAXN];     // deg during count; row-end after fill
__device__ int   g_bsums[SCAN_BLK];
__device__ int2  g_edges[MAXE];      // (src, __float_as_int(ew)) CSR by dst

// Packed f32x2 helpers (Blackwell sm_100+)
#define FFMA2(acc, a, b) \
    asm("fma.rn.f32x2 %0, %1, %2, %0;" : "+l"(acc) : "l"(a), "l"(b))
#define PACK_DUP(out, x) \
    asm("mov.b64 %0, {%1, %1};" : "=l"(out) : "r"(x))
#define UNPACK2(lo, hi, in) \
    asm("mov.b64 {%0, %1}, %2;" : "=f"(lo), "=f"(hi) : "l"(in))

// ---------------------------------------------------------------------------
// GEMM: out[M,128] = f_in(A) @ W, with optional fused epilogues.
//   in_mode : 0 = A as-is; 1 = relu(A + ib); 2 = A + ib (NO relu)
//   out_mode: 0 = store acc; 2 = gate: g[r] = sum_j relu(acc_j+ob_j)*gw2_j + gb2
// Inner loop uses packed fma.rn.f32x2 (FFMA2): lane owns 4 cols = 2 packed
// accumulators per row; W pairs come packed free from the float4 smem load.
// ---------------------------------------------------------------------------
#define ROWS_PER_WARP 8
#define GEMM_WARPS 8
#define ROWS_PER_BLK (ROWS_PER_WARP * GEMM_WARPS)   // 64

__global__ __launch_bounds__(256) void gemm128_kernel(
    const float* __restrict__ A, const float* __restrict__ W,
    const float* __restrict__ ib, const float* __restrict__ ob,
    const float* __restrict__ gw2, const float* __restrict__ gb2,
    float* __restrict__ out, float* __restrict__ gate,
    int M, int in_mode, int out_mode)
{
    extern __shared__ float sh[];
    float* Wsh  = sh;                  // D*D floats (64KB)
    float* rows = sh + D * D;          // ROWS_PER_BLK * D floats (32KB)

    for (int i = threadIdx.x; i < D * D; i += blockDim.x) Wsh[i] = W[i];

    const int warp = threadIdx.x >> 5;
    const int lane = threadIdx.x & 31;
    const int col  = lane << 2;

    float ob0 = 0.f, ob1 = 0.f, ob2v = 0.f, ob3 = 0.f;
    float w20 = 0.f, w21 = 0.f, w22 = 0.f, w23 = 0.f, gb2v = 0.f;
    if (out_mode == 2) {
        ob0 = ob[col]; ob1 = ob[col + 1]; ob2v = ob[col + 2]; ob3 = ob[col + 3];
        w20 = gw2[col]; w21 = gw2[col + 1]; w22 = gw2[col + 2]; w23 = gw2[col + 3];
        gb2v = gb2[0];
    }
    __syncthreads();

    const int ngroups = (M + ROWS_PER_BLK - 1) / ROWS_PER_BLK;
    for (int grp = blockIdx.x; grp < ngroups; grp += gridDim.x) {
        const int r0 = grp * ROWS_PER_BLK;

        {
            const int nf4 = ROWS_PER_BLK * (D / 4);
            for (int i = threadIdx.x; i < nf4; i += blockDim.x) {
                const int rr = i >> 5;
                const int cc = (i & 31) << 2;
                const int r  = r0 + rr;
                float4 v = make_float4(0.f, 0.f, 0.f, 0.f);
                if (r < M) v = *(const float4*)&A[(size_t)r * D + cc];
                if (in_mode) {
                    v.x += ib[cc];     v.y += ib[cc + 1];
                    v.z += ib[cc + 2]; v.w += ib[cc + 3];
                    if (in_mode == 1) {
                        v.x = fmaxf(v.x, 0.f); v.y = fmaxf(v.y, 0.f);
                        v.z = fmaxf(v.z, 0.f); v.w = fmaxf(v.w, 0.f);
                    }
                }
                *(float4*)&rows[rr * D + cc] = v;
            }
        }
        __syncthreads();

        // Packed accumulators: [row][pair], pair0 = cols (col,col+1), pair1 = (col+2,col+3)
        unsigned long long acc[ROWS_PER_WARP][2];
        #pragma unroll
        for (int r = 0; r < ROWS_PER_WARP; r++) { acc[r][0] = 0ull; acc[r][1] = 0ull; }

        const float* rb = &rows[warp * ROWS_PER_WARP * D];
        #pragma unroll 2
        for (int k = 0; k < D; k += 2) {
            // W rows k and k+1, 4 cols each -> 2 packed pairs per row (free from LDS.128)
            const ulonglong2 wA = *(const ulonglong2*)&Wsh[k * D + col];
            const ulonglong2 wB = *(const ulonglong2*)&Wsh[(k + 1) * D + col];
            #pragma unroll
            for (int r = 0; r < ROWS_PER_WARP; r++) {
                const float2 a2 = *(const float2*)&rb[r * D + k];   // a[k], a[k+1]
                unsigned long long a0, a1;
                PACK_DUP(a0, __float_as_uint(a2.x));
                PACK_DUP(a1, __float_as_uint(a2.y));
                FFMA2(acc[r][0], a0, wA.x);
                FFMA2(acc[r][1], a0, wA.y);
                FFMA2(acc[r][0], a1, wB.x);
                FFMA2(acc[r][1], a1, wB.y);
            }
        }

        if (out_mode == 0) {
            #pragma unroll
            for (int r = 0; r < ROWS_PER_WARP; r++) {
                const int row = r0 + warp * ROWS_PER_WARP + r;
                if (row < M) {
                    float4 o;
                    UNPACK2(o.x, o.y, acc[r][0]);
                    UNPACK2(o.z, o.w, acc[r][1]);
                    *(float4*)&out[(size_t)row * D + col] = o;
                }
            }
        } else {
            #pragma unroll
            for (int r = 0; r < ROWS_PER_WARP; r++) {
                const int row = r0 + warp * ROWS_PER_WARP + r;
                float a0, a1, a2v, a3;
                UNPACK2(a0, a1, acc[r][0]);
                UNPACK2(a2v, a3, acc[r][1]);
                float v = fmaxf(a0 + ob0, 0.f) * w20
                        + fmaxf(a1 + ob1, 0.f) * w21
                        + fmaxf(a2v + ob2v, 0.f) * w22
                        + fmaxf(a3 + ob3, 0.f) * w23;
                #pragma unroll
                for (int o = 16; o; o >>= 1) v += __shfl_xor_sync(0xffffffffu, v, o);
                if (lane == 0 && row < M) gate[row] = v + gb2v;
            }
        }
        __syncthreads();
    }
}

// ---------------------------------------------------------------------------
// CSR build: degree count -> exclusive scan -> bucket fill
// ---------------------------------------------------------------------------
__global__ __launch_bounds__(256) void deg_kernel(
    const int* __restrict__ dst, int* __restrict__ deg, int NE)
{
    for (int e = blockIdx.x * 256 + threadIdx.x; e < NE; e += gridDim.x * 256)
        atomicAdd(&deg[dst[e]], 1);
}

__global__ __launch_bounds__(SCAN_BLK) void scanA_kernel(
    const int* __restrict__ deg, int* __restrict__ rowptr,
    int* __restrict__ bsums, int n)
{
    __shared__ int s[SCAN_BLK];
    const int t = threadIdx.x;
    const int i = blockIdx.x * SCAN_BLK + t;
    const int v = (i < n) ? deg[i] : 0;
    s[t] = v;
    __syncthreads();
    #pragma unroll
    for (int o = 1; o < SCAN_BLK; o <<= 1) {
        const int add = (t >= o) ? s[t - o] : 0;
        __syncthreads();
        s[t] += add;
        __syncthreads();
    }
    if (i < n) rowptr[i] = s[t] - v;          // exclusive
    if (t == SCAN_BLK - 1) bsums[blockIdx.x] = s[t];
}

__global__ __launch_bounds__(SCAN_BLK) void scanB_kernel(int* __restrict__ bsums, int nblk)
{
    __shared__ int s[SCAN_BLK];
    const int t = threadIdx.x;
    const int v = (t < nblk) ? bsums[t] : 0;
    s[t] = v;
    __syncthreads();
    #pragma unroll
    for (int o = 1; o < SCAN_BLK; o <<= 1) {
        const int add = (t >= o) ? s[t - o] : 0;
        __syncthreads();
        s[t] += add;
        __syncthreads();
    }
    if (t < nblk) bsums[t] = s[t] - v;        // exclusive
}

__global__ __launch_bounds__(SCAN_BLK) void scanC_kernel(
    int* __restrict__ rowptr, int* __restrict__ cursor,
    const int* __restrict__ bsums, int n)
{
    const int i = blockIdx.x * SCAN_BLK + threadIdx.x;
    if (i < n) {
        const int r = rowptr[i] + bsums[blockIdx.x];
        rowptr[i] = r;
        cursor[i] = r;
    }
}

__global__ __launch_bounds__(256) void fill_kernel(
    const int* __restrict__ src, const int* __restrict__ dst,
    const float* __restrict__ ew, int* __restrict__ cursor,
    int2* __restrict__ edges, int NE)
{
    for (int e = blockIdx.x * 256 + threadIdx.x; e < NE; e += gridDim.x * 256) {
        const int p = atomicAdd(&cursor[dst[e]], 1);
        edges[p] = make_int2(src[e], __float_as_int(ew[e]));
    }
}

// ---------------------------------------------------------------------------
// CSR gather-aggregate: out[n,:] = sum_{e in csr[n]} ew_e * A[src_e, :]
// One warp per node; lane owns one float4 column slice.
// ---------------------------------------------------------------------------
__global__ __launch_bounds__(256) void gather_kernel(
    const float* __restrict__ A, const int* __restrict__ rowptr,
    const int* __restrict__ rowend, const int2* __restrict__ edges,
    float* __restrict__ out, int M)
{
    const int node = ((blockIdx.x * 256 + threadIdx.x) >> 5);
    if (node >= M) return;
    const int lane = threadIdx.x & 31;
    const int col  = lane << 2;

    const int start = rowptr[node];
    const int end   = rowend[node];

    float4 acc = make_float4(0.f, 0.f, 0.f, 0.f);
    int2 e_next = (start < end) ? edges[start] : make_int2(0, 0);
    for (int j = start; j < end; j++) {
        const int2 e = e_next;
        if (j + 1 < end) e_next = edges[j + 1];        // prefetch next edge
        const float w = __int_as_float(e.y);
        const float4 v = *(const float4*)&A[(size_t)e.x * D + col];
        acc.x = fmaf(w, v.x, acc.x);
        acc.y = fmaf(w, v.y, acc.y);
        acc.z = fmaf(w, v.z, acc.z);
        acc.w = fmaf(w, v.w, acc.w);
    }
    *(float4*)&out[(size_t)node * D + col] = acc;
}

// ---------------------------------------------------------------------------
// Per-graph softmax attention pool + final MLP, one block per graph.
// ---------------------------------------------------------------------------
#define EBUF_CAP 4096
__global__ __launch_bounds__(128) void attn_kernel(
    const float* __restrict__ T1, const float* __restrict__ b2,
    const float* __restrict__ gate, const int* __restrict__ batch,
    const float* __restrict__ l1W, const float* __restrict__ l1b,
    const float* __restrict__ l2W, const float* __restrict__ l2b,
    float* __restrict__ out, int M)
{
    __shared__ float ebuf[EBUF_CAP];
    __shared__ float sacc[D];
    __shared__ float red[4];
    __shared__ int bounds[2];

    const int b    = blockIdx.x;
    const int tid  = threadIdx.x;
    const int lane = tid & 31;
    const int warp = tid >> 5;

    if (tid < 2) {
        const int target = b + tid;
        int lo = 0, hi = M;
        while (lo < hi) {
            const int mid = (lo + hi) >> 1;
            if (batch[mid] < target) lo = mid + 1; else hi = mid;
        }
        bounds[tid] = lo;
    }
    __syncthreads();
    const int lo  = bounds[0];
    const int hi  = bounds[1];
    const int len = hi - lo;

    float m = -INFINITY;
    for (int i = tid; i < len; i += D) m = fmaxf(m, gate[lo + i]);
    #pragma unroll
    for (int o = 16; o; o >>= 1) m = fmaxf(m, __shfl_xor_sync(0xffffffffu, m, o));
    if (lane == 0) red[warp] = m;
    __syncthreads();
    m = fmaxf(fmaxf(red[0], red[1]), fmaxf(red[2], red[3]));
    __syncthreads();

    float s = 0.f;
    for (int i = tid; i < len; i += D) {
        const float e = expf(gate[lo + i] - m);
        if (i < EBUF_CAP) ebuf[i] = e;
        s += e;
    }
    #pragma unroll
    for (int o = 16; o; o >>= 1) s += __shfl_xor_sync(0xffffffffu, s, o);
    if (lane == 0) red[warp] = s;
    __syncthreads();
    const float denom = red[0] + red[1] + red[2] + red[3];
    const float inv = 1.f / (denom + 1e-16f);

    float acc = 0.f;
    const float b2c = b2[tid];
    for (int i = 0; i < len; i++) {
        const float w = (i < EBUF_CAP) ? ebuf[i] : expf(gate[lo + i] - m);
        acc = fmaf(w, T1[(size_t)(lo + i) * D + tid] + b2c, acc);
    }
    acc *= inv;
    __syncthreads();
    sacc[tid] = acc;
    __syncthreads();

    float u = l1b[tid];
    #pragma unroll 8
    for (int k = 0; k < D; k++) u = fmaf(sacc[k], l1W[k * D + tid], u);
    u = fmaxf(u, 0.f) * l2W[tid];
    #pragma unroll
    for (int o = 16; o; o >>= 1) u += __shfl_xor_sync(0xffffffffu, u, o);
    if (lane == 0) red[warp] = u;
    __syncthreads();
    if (tid == 0) out[b] = red[0] + red[1] + red[2] + red[3] + l2b[0];
}

// ---------------------------------------------------------------------------
extern "C" void kernel_launch(void* const* d_in, const int* in_sizes, int n_in,
                              void* d_out, int out_size)
{
    const float* x     = (const float*)d_in[0];
    const int*   ei    = (const int*)  d_in[1];
    const float* ea    = (const float*)d_in[2];
    const int*   batch = (const int*)  d_in[3];
    const float* W1    = (const float*)d_in[4];
    const float* b1    = (const float*)d_in[5];
    const float* W2    = (const float*)d_in[6];
    const float* b2    = (const float*)d_in[7];
    const float* gW1   = (const float*)d_in[8];
    const float* gb1   = (const float*)d_in[9];
    const float* gW2   = (const float*)d_in[10];
    const float* gb2   = (const float*)d_in[11];
    const float* l1W   = (const float*)d_in[12];
    const float* l1b   = (const float*)d_in[13];
    const float* l2W   = (const float*)d_in[14];
    const float* l2b   = (const float*)d_in[15];
    float* out = (float*)d_out;

    const int M  = in_sizes[0] / D;
    const int NE = in_sizes[1] / 2;
    const int* src = ei;
    const int* dst = ei + NE;

    float *t0, *t1, *gate;
    int *rowptr, *cursor, *bsums;
    int2 *edges;
    cudaGetSymbolAddress((void**)&t0,     g_t0);
    cudaGetSymbolAddress((void**)&t1,     g_t1);
    cudaGetSymbolAddress((void**)&gate,   g_gate);
    cudaGetSymbolAddress((void**)&rowptr, g_rowptr);
    cudaGetSymbolAddress((void**)&cursor, g_cursor);
    cudaGetSymbolAddress((void**)&bsums,  g_bsums);
    cudaGetSymbolAddress((void**)&edges,  g_edges);

    const size_t SMEM = (size_t)(D * D + ROWS_PER_BLK * D) * sizeof(float); // 96KB
    cudaFuncSetAttribute(gemm128_kernel, cudaFuncAttributeMaxDynamicSharedMemorySize, (int)SMEM);

    const int GB     = 296;                       // 2 blocks/SM for GEMM
    const int EBLK   = 2048;                      // edge-parallel kernels (grid-stride)
    const int NBLK   = (M + SCAN_BLK - 1) / SCAN_BLK;   // scan blocks (<= SCAN_BLK)
    const int GATB   = (M * 32 + 255) / 256;      // warp-per-node gather

    // ---- CSR build (once; reused by both convs) ----
    cudaMemsetAsync(cursor, 0, (size_t)M * sizeof(int), 0);
    deg_kernel <<<EBLK, 256>>>(dst, cursor, NE);
    scanA_kernel<<<NBLK, SCAN_BLK>>>(cursor, rowptr, bsums, M);
    scanB_kernel<<<1, SCAN_BLK>>>(bsums, NBLK);
    scanC_kernel<<<NBLK, SCAN_BLK>>>(rowptr, cursor, bsums, M);
    fill_kernel<<<EBLK, 256>>>(src, dst, ea, cursor, edges, NE);
    // after fill: cursor[n] = row end

    // conv1: t0 = x @ W1 ; t1 = csr_gather(t0)
    gemm128_kernel<<<GB, 256, SMEM>>>(x, W1, nullptr, nullptr, nullptr, nullptr,
                                      t0, nullptr, M, 0, 0);
    gather_kernel<<<GATB, 256>>>(t0, rowptr, cursor, edges, t1, M);

    // conv2: t0 = relu(t1 + b1) @ W2 ; t1 = csr_gather(t0)
    gemm128_kernel<<<GB, 256, SMEM>>>(t1, W2, b1, nullptr, nullptr, nullptr,
                                      t0, nullptr, M, 1, 0);
    gather_kernel<<<GATB, 256>>>(t0, rowptr, cursor, edges, t1, M);

    // gate[r] = relu((t1[r]+b2) @ gW1 + gb1) . gW2 + gb2
    gemm128_kernel<<<GB, 256, SMEM>>>(t1, gW1, b2, gb1, gW2, gb2,
                                      nullptr, gate, M, 2, 2);

    // per-graph softmax pool + final MLP
    attn_kernel<<<NGRAPH, 128>>>(t1, b2, gate, batch, l1W, l1b, l2W, l2b, out, M);
}

// round 10
// speedup vs baseline: 1.3213x; 1.0333x over previous
#include <cuda_runtime.h>
#include <math.h>

#define D 128
#define NGRAPH 128
#define MAXN 100000
#define MAXE 1600000
#define SCAN_BLK 512

// Scratch (static __device__ arrays per allocation rules)
__device__ float g_t0[(size_t)MAXN * D];
__device__ float g_t1[(size_t)MAXN * D];
__device__ float g_gate[MAXN];
__device__ int   g_rowptr[MAXN];
__device__ int   g_cursor[MAXN];     // deg during count; row-end after fill
__device__ int   g_bsums[SCAN_BLK];
__device__ int2  g_edges[MAXE];      // (src, __float_as_int(ew)) CSR by dst

// Packed f32x2 helpers (Blackwell sm_100+)
#define FFMA2(acc, a, b) \
    asm("fma.rn.f32x2 %0, %1, %2, %0;" : "+l"(acc) : "l"(a), "l"(b))
#define PACK_DUP(out, x) \
    asm("mov.b64 %0, {%1, %1};" : "=l"(out) : "r"(x))
#define UNPACK2(lo, hi, in) \
    asm("mov.b64 {%0, %1}, %2;" : "=f"(lo), "=f"(hi) : "l"(in))

// ---------------------------------------------------------------------------
// GEMM: out[M,128] = f_in(A) @ W, with optional fused epilogues.
//   in_mode : 0 = A as-is; 1 = relu(A + ib); 2 = A + ib (NO relu)
//   out_mode: 0 = store acc; 2 = gate: g[r] = sum_j relu(acc_j+ob_j)*gw2_j + gb2
// ---------------------------------------------------------------------------
#define ROWS_PER_WARP 8
#define GEMM_WARPS 8
#define ROWS_PER_BLK (ROWS_PER_WARP * GEMM_WARPS)   // 64

__global__ __launch_bounds__(256) void gemm128_kernel(
    const float* __restrict__ A, const float* __restrict__ W,
    const float* __restrict__ ib, const float* __restrict__ ob,
    const float* __restrict__ gw2, const float* __restrict__ gb2,
    float* __restrict__ out, float* __restrict__ gate,
    int M, int in_mode, int out_mode)
{
    extern __shared__ float sh[];
    float* Wsh  = sh;                  // D*D floats (64KB)
    float* rows = sh + D * D;          // ROWS_PER_BLK * D floats (32KB)

    for (int i = threadIdx.x; i < D * D; i += blockDim.x) Wsh[i] = W[i];

    const int warp = threadIdx.x >> 5;
    const int lane = threadIdx.x & 31;
    const int col  = lane << 2;

    float ob0 = 0.f, ob1 = 0.f, ob2v = 0.f, ob3 = 0.f;
    float w20 = 0.f, w21 = 0.f, w22 = 0.f, w23 = 0.f, gb2v = 0.f;
    if (out_mode == 2) {
        ob0 = ob[col]; ob1 = ob[col + 1]; ob2v = ob[col + 2]; ob3 = ob[col + 3];
        w20 = gw2[col]; w21 = gw2[col + 1]; w22 = gw2[col + 2]; w23 = gw2[col + 3];
        gb2v = gb2[0];
    }
    __syncthreads();

    const int ngroups = (M + ROWS_PER_BLK - 1) / ROWS_PER_BLK;
    for (int grp = blockIdx.x; grp < ngroups; grp += gridDim.x) {
        const int r0 = grp * ROWS_PER_BLK;

        {
            const int nf4 = ROWS_PER_BLK * (D / 4);
            for (int i = threadIdx.x; i < nf4; i += blockDim.x) {
                const int rr = i >> 5;
                const int cc = (i & 31) << 2;
                const int r  = r0 + rr;
                float4 v = make_float4(0.f, 0.f, 0.f, 0.f);
                if (r < M) v = *(const float4*)&A[(size_t)r * D + cc];
                if (in_mode) {
                    v.x += ib[cc];     v.y += ib[cc + 1];
                    v.z += ib[cc + 2]; v.w += ib[cc + 3];
                    if (in_mode == 1) {
                        v.x = fmaxf(v.x, 0.f); v.y = fmaxf(v.y, 0.f);
                        v.z = fmaxf(v.z, 0.f); v.w = fmaxf(v.w, 0.f);
                    }
                }
                *(float4*)&rows[rr * D + cc] = v;
            }
        }
        __syncthreads();

        // Packed accumulators: [row][pair]
        unsigned long long acc[ROWS_PER_WARP][2];
        #pragma unroll
        for (int r = 0; r < ROWS_PER_WARP; r++) { acc[r][0] = 0ull; acc[r][1] = 0ull; }

        const float* rb = &rows[warp * ROWS_PER_WARP * D];
        #pragma unroll 2
        for (int k = 0; k < D; k += 2) {
            const ulonglong2 wA = *(const ulonglong2*)&Wsh[k * D + col];
            const ulonglong2 wB = *(const ulonglong2*)&Wsh[(k + 1) * D + col];
            #pragma unroll
            for (int r = 0; r < ROWS_PER_WARP; r++) {
                const float2 a2 = *(const float2*)&rb[r * D + k];
                unsigned long long a0, a1;
                PACK_DUP(a0, __float_as_uint(a2.x));
                PACK_DUP(a1, __float_as_uint(a2.y));
                FFMA2(acc[r][0], a0, wA.x);
                FFMA2(acc[r][1], a0, wA.y);
                FFMA2(acc[r][0], a1, wB.x);
                FFMA2(acc[r][1], a1, wB.y);
            }
        }

        if (out_mode == 0) {
            #pragma unroll
            for (int r = 0; r < ROWS_PER_WARP; r++) {
                const int row = r0 + warp * ROWS_PER_WARP + r;
                if (row < M) {
                    float4 o;
                    UNPACK2(o.x, o.y, acc[r][0]);
                    UNPACK2(o.z, o.w, acc[r][1]);
                    *(float4*)&out[(size_t)row * D + col] = o;
                }
            }
        } else {
            #pragma unroll
            for (int r = 0; r < ROWS_PER_WARP; r++) {
                const int row = r0 + warp * ROWS_PER_WARP + r;
                float a0, a1, a2v, a3;
                UNPACK2(a0, a1, acc[r][0]);
                UNPACK2(a2v, a3, acc[r][1]);
                float v = fmaxf(a0 + ob0, 0.f) * w20
                        + fmaxf(a1 + ob1, 0.f) * w21
                        + fmaxf(a2v + ob2v, 0.f) * w22
                        + fmaxf(a3 + ob3, 0.f) * w23;
                #pragma unroll
                for (int o = 16; o; o >>= 1) v += __shfl_xor_sync(0xffffffffu, v, o);
                if (lane == 0 && row < M) gate[row] = v + gb2v;
            }
        }
        __syncthreads();
    }
}

// ---------------------------------------------------------------------------
// CSR build: degree count -> exclusive scan -> bucket fill
// ---------------------------------------------------------------------------
__global__ __launch_bounds__(256) void deg_kernel(
    const int* __restrict__ dst, int* __restrict__ deg, int NE)
{
    for (int e = blockIdx.x * 256 + threadIdx.x; e < NE; e += gridDim.x * 256)
        atomicAdd(&deg[dst[e]], 1);
}

__global__ __launch_bounds__(SCAN_BLK) void scanA_kernel(
    const int* __restrict__ deg, int* __restrict__ rowptr,
    int* __restrict__ bsums, int n)
{
    __shared__ int s[SCAN_BLK];
    const int t = threadIdx.x;
    const int i = blockIdx.x * SCAN_BLK + t;
    const int v = (i < n) ? deg[i] : 0;
    s[t] = v;
    __syncthreads();
    #pragma unroll
    for (int o = 1; o < SCAN_BLK; o <<= 1) {
        const int add = (t >= o) ? s[t - o] : 0;
        __syncthreads();
        s[t] += add;
        __syncthreads();
    }
    if (i < n) rowptr[i] = s[t] - v;          // exclusive
    if (t == SCAN_BLK - 1) bsums[blockIdx.x] = s[t];
}

__global__ __launch_bounds__(SCAN_BLK) void scanB_kernel(int* __restrict__ bsums, int nblk)
{
    __shared__ int s[SCAN_BLK];
    const int t = threadIdx.x;
    const int v = (t < nblk) ? bsums[t] : 0;
    s[t] = v;
    __syncthreads();
    #pragma unroll
    for (int o = 1; o < SCAN_BLK; o <<= 1) {
        const int add = (t >= o) ? s[t - o] : 0;
        __syncthreads();
        s[t] += add;
        __syncthreads();
    }
    if (t < nblk) bsums[t] = s[t] - v;        // exclusive
}

__global__ __launch_bounds__(SCAN_BLK) void scanC_kernel(
    int* __restrict__ rowptr, int* __restrict__ cursor,
    const int* __restrict__ bsums, int n)
{
    const int i = blockIdx.x * SCAN_BLK + threadIdx.x;
    if (i < n) {
        const int r = rowptr[i] + bsums[blockIdx.x];
        rowptr[i] = r;
        cursor[i] = r;
    }
}

__global__ __launch_bounds__(256) void fill_kernel(
    const int* __restrict__ src, const int* __restrict__ dst,
    const float* __restrict__ ew, int* __restrict__ cursor,
    int2* __restrict__ edges, int NE)
{
    for (int e = blockIdx.x * 256 + threadIdx.x; e < NE; e += gridDim.x * 256) {
        const int p = atomicAdd(&cursor[dst[e]], 1);
        edges[p] = make_int2(src[e], __float_as_int(ew[e]));
    }
}

// ---------------------------------------------------------------------------
// CSR gather-aggregate: out[n,:] = sum_{e in csr[n]} ew_e * A[src_e, :]
// One warp per node; lane owns one float4 column slice.
// Edge loop unrolled x4 -> 4 independent feature loads in flight (MLP=4).
// ---------------------------------------------------------------------------
__global__ __launch_bounds__(256) void gather_kernel(
    const float* __restrict__ A, const int* __restrict__ rowptr,
    const int* __restrict__ rowend, const int2* __restrict__ edges,
    float* __restrict__ out, int M)
{
    const int node = ((blockIdx.x * 256 + threadIdx.x) >> 5);
    if (node >= M) return;
    const int lane = threadIdx.x & 31;
    const int col  = lane << 2;

    const int start = rowptr[node];
    const int end   = rowend[node];

    float4 acc0 = make_float4(0.f, 0.f, 0.f, 0.f);
    float4 acc1 = make_float4(0.f, 0.f, 0.f, 0.f);

    int j = start;
    for (; j + 4 <= end; j += 4) {
        const int2 e0 = edges[j];
        const int2 e1 = edges[j + 1];
        const int2 e2 = edges[j + 2];
        const int2 e3 = edges[j + 3];
        const float4 v0 = *(const float4*)&A[(size_t)e0.x * D + col];
        const float4 v1 = *(const float4*)&A[(size_t)e1.x * D + col];
        const float4 v2 = *(const float4*)&A[(size_t)e2.x * D + col];
        const float4 v3 = *(const float4*)&A[(size_t)e3.x * D + col];
        const float w0 = __int_as_float(e0.y);
        const float w1 = __int_as_float(e1.y);
        const float w2 = __int_as_float(e2.y);
        const float w3 = __int_as_float(e3.y);
        acc0.x = fmaf(w0, v0.x, acc0.x); acc0.y = fmaf(w0, v0.y, acc0.y);
        acc0.z = fmaf(w0, v0.z, acc0.z); acc0.w = fmaf(w0, v0.w, acc0.w);
        acc1.x = fmaf(w1, v1.x, acc1.x); acc1.y = fmaf(w1, v1.y, acc1.y);
        acc1.z = fmaf(w1, v1.z, acc1.z); acc1.w = fmaf(w1, v1.w, acc1.w);
        acc0.x = fmaf(w2, v2.x, acc0.x); acc0.y = fmaf(w2, v2.y, acc0.y);
        acc0.z = fmaf(w2, v2.z, acc0.z); acc0.w = fmaf(w2, v2.w, acc0.w);
        acc1.x = fmaf(w3, v3.x, acc1.x); acc1.y = fmaf(w3, v3.y, acc1.y);
        acc1.z = fmaf(w3, v3.z, acc1.z); acc1.w = fmaf(w3, v3.w, acc1.w);
    }
    for (; j < end; j++) {
        const int2 e = edges[j];
        const float w = __int_as_float(e.y);
        const float4 v = *(const float4*)&A[(size_t)e.x * D + col];
        acc0.x = fmaf(w, v.x, acc0.x); acc0.y = fmaf(w, v.y, acc0.y);
        acc0.z = fmaf(w, v.z, acc0.z); acc0.w = fmaf(w, v.w, acc0.w);
    }

    acc0.x += acc1.x; acc0.y += acc1.y; acc0.z += acc1.z; acc0.w += acc1.w;
    *(float4*)&out[(size_t)node * D + col] = acc0;
}

// ---------------------------------------------------------------------------
// Per-graph softmax attention pool + final MLP, one block per graph.
// ---------------------------------------------------------------------------
#define EBUF_CAP 4096
__global__ __launch_bounds__(128) void attn_kernel(
    const float* __restrict__ T1, const float* __restrict__ b2,
    const float* __restrict__ gate, const int* __restrict__ batch,
    const float* __restrict__ l1W, const float* __restrict__ l1b,
    const float* __restrict__ l2W, const float* __restrict__ l2b,
    float* __restrict__ out, int M)
{
    __shared__ float ebuf[EBUF_CAP];
    __shared__ float sacc[D];
    __shared__ float red[4];
    __shared__ int bounds[2];

    const int b    = blockIdx.x;
    const int tid  = threadIdx.x;
    const int lane = tid & 31;
    const int warp = tid >> 5;

    if (tid < 2) {
        const int target = b + tid;
        int lo = 0, hi = M;
        while (lo < hi) {
            const int mid = (lo + hi) >> 1;
            if (batch[mid] < target) lo = mid + 1; else hi = mid;
        }
        bounds[tid] = lo;
    }
    __syncthreads();
    const int lo  = bounds[0];
    const int hi  = bounds[1];
    const int len = hi - lo;

    float m = -INFINITY;
    for (int i = tid; i < len; i += D) m = fmaxf(m, gate[lo + i]);
    #pragma unroll
    for (int o = 16; o; o >>= 1) m = fmaxf(m, __shfl_xor_sync(0xffffffffu, m, o));
    if (lane == 0) red[warp] = m;
    __syncthreads();
    m = fmaxf(fmaxf(red[0], red[1]), fmaxf(red[2], red[3]));
    __syncthreads();

    float s = 0.f;
    for (int i = tid; i < len; i += D) {
        const float e = expf(gate[lo + i] - m);
        if (i < EBUF_CAP) ebuf[i] = e;
        s += e;
    }
    #pragma unroll
    for (int o = 16; o; o >>= 1) s += __shfl_xor_sync(0xffffffffu, s, o);
    if (lane == 0) red[warp] = s;
    __syncthreads();
    const float denom = red[0] + red[1] + red[2] + red[3];
    const float inv = 1.f / (denom + 1e-16f);

    float acc = 0.f;
    const float b2c = b2[tid];
    for (int i = 0; i < len; i++) {
        const float w = (i < EBUF_CAP) ? ebuf[i] : expf(gate[lo + i] - m);
        acc = fmaf(w, T1[(size_t)(lo + i) * D + tid] + b2c, acc);
    }
    acc *= inv;
    __syncthreads();
    sacc[tid] = acc;
    __syncthreads();

    float u = l1b[tid];
    #pragma unroll 8
    for (int k = 0; k < D; k++) u = fmaf(sacc[k], l1W[k * D + tid], u);
    u = fmaxf(u, 0.f) * l2W[tid];
    #pragma unroll
    for (int o = 16; o; o >>= 1) u += __shfl_xor_sync(0xffffffffu, u, o);
    if (lane == 0) red[warp] = u;
    __syncthreads();
    if (tid == 0) out[b] = red[0] + red[1] + red[2] + red[3] + l2b[0];
}

// ---------------------------------------------------------------------------
extern "C" void kernel_launch(void* const* d_in, const int* in_sizes, int n_in,
                              void* d_out, int out_size)
{
    const float* x     = (const float*)d_in[0];
    const int*   ei    = (const int*)  d_in[1];
    const float* ea    = (const float*)d_in[2];
    const int*   batch = (const int*)  d_in[3];
    const float* W1    = (const float*)d_in[4];
    const float* b1    = (const float*)d_in[5];
    const float* W2    = (const float*)d_in[6];
    const float* b2    = (const float*)d_in[7];
    const float* gW1   = (const float*)d_in[8];
    const float* gb1   = (const float*)d_in[9];
    const float* gW2   = (const float*)d_in[10];
    const float* gb2   = (const float*)d_in[11];
    const float* l1W   = (const float*)d_in[12];
    const float* l1b   = (const float*)d_in[13];
    const float* l2W   = (const float*)d_in[14];
    const float* l2b   = (const float*)d_in[15];
    float* out = (float*)d_out;

    const int M  = in_sizes[0] / D;
    const int NE = in_sizes[1] / 2;
    const int* src = ei;
    const int* dst = ei + NE;

    float *t0, *t1, *gate;
    int *rowptr, *cursor, *bsums;
    int2 *edges;
    cudaGetSymbolAddress((void**)&t0,     g_t0);
    cudaGetSymbolAddress((void**)&t1,     g_t1);
    cudaGetSymbolAddress((void**)&gate,   g_gate);
    cudaGetSymbolAddress((void**)&rowptr, g_rowptr);
    cudaGetSymbolAddress((void**)&cursor, g_cursor);
    cudaGetSymbolAddress((void**)&bsums,  g_bsums);
    cudaGetSymbolAddress((void**)&edges,  g_edges);

    const size_t SMEM = (size_t)(D * D + ROWS_PER_BLK * D) * sizeof(float); // 96KB
    cudaFuncSetAttribute(gemm128_kernel, cudaFuncAttributeMaxDynamicSharedMemorySize, (int)SMEM);

    const int GB     = 296;                       // 2 blocks/SM for GEMM
    const int EBLK   = 2048;                      // edge-parallel kernels (grid-stride)
    const int NBLK   = (M + SCAN_BLK - 1) / SCAN_BLK;   // scan blocks (<= SCAN_BLK)
    const int GATB   = (M * 32 + 255) / 256;      // warp-per-node gather

    // ---- CSR build (once; reused by both convs) ----
    cudaMemsetAsync(cursor, 0, (size_t)M * sizeof(int), 0);
    deg_kernel <<<EBLK, 256>>>(dst, cursor, NE);
    scanA_kernel<<<NBLK, SCAN_BLK>>>(cursor, rowptr, bsums, M);
    scanB_kernel<<<1, SCAN_BLK>>>(bsums, NBLK);
    scanC_kernel<<<NBLK, SCAN_BLK>>>(rowptr, cursor, bsums, M);
    fill_kernel<<<EBLK, 256>>>(src, dst, ea, cursor, edges, NE);
    // after fill: cursor[n] = row end

    // conv1: t0 = x @ W1 ; t1 = csr_gather(t0)
    gemm128_kernel<<<GB, 256, SMEM>>>(x, W1, nullptr, nullptr, nullptr, nullptr,
                                      t0, nullptr, M, 0, 0);
    gather_kernel<<<GATB, 256>>>(t0, rowptr, cursor, edges, t1, M);

    // conv2: t0 = relu(t1 + b1) @ W2 ; t1 = csr_gather(t0)
    gemm128_kernel<<<GB, 256, SMEM>>>(t1, W2, b1, nullptr, nullptr, nullptr,
                                      t0, nullptr, M, 1, 0);
    gather_kernel<<<GATB, 256>>>(t0, rowptr, cursor, edges, t1, M);

    // gate[r] = relu((t1[r]+b2) @ gW1 + gb1) . gW2 + gb2
    gemm128_kernel<<<GB, 256, SMEM>>>(t1, gW1, b2, gb1, gW2, gb2,
                                      nullptr, gate, M, 2, 2);

    // per-graph softmax pool + final MLP
    attn_kernel<<<NGRAPH, 128>>>(t1, b2, gate, batch, l1W, l1b, l2W, l2b, out, M);
}